// round 5
// baseline (speedup 1.0000x reference)
#include <cuda_runtime.h>
#include <cuda_bf16.h>
#include <cstdint>

// ===================== problem constants =====================
#define MROWS 32768
#define NDIM  1024
#define XE    (MROWS * NDIM)       // 33,554,432
#define WE    (NDIM * NDIM)        // 1,048,576
#define NTHREADS 512
#define NCTAS    512               // 256 clusters x 2

// bf16 scratch (static __device__ globals: the sanctioned no-alloc workaround)
__device__ __nv_bfloat16 g_xb[XE];
__device__ __nv_bfloat16 g_wb[WE];

// ===================== smem layout (bytes) =====================
#define OFF_BIAS 0                 // 512 f32
#define OFF_S    2048              // 128 f32 partial expsum
#define OFF_INV  2560              // 128 f32 1/S
#define OFF_A    4096              // 2 stages x 10240 (128 rows x 80B padded)
#define A_STG    10240
#define OFF_B    24576             // 2 stages x 20480 (256 rows x 80B padded)
#define B_STG    20480
#define OFF_L    65536             // 128 x 1040B logits (520 bf16/row, padded)
#define L_STRIDE 1040
#define SMEM_TOTAL 198656

// ===================== helpers =====================
static __device__ __forceinline__ uint32_t smem_u32(const void* p) {
    uint32_t a;
    asm("{ .reg .u64 t; cvta.to.shared.u64 t, %1; cvt.u32.u64 %0, t; }" : "=r"(a) : "l"(p));
    return a;
}

#define CP_ASYNC16(dst, src) \
    asm volatile("cp.async.cg.shared.global [%0], [%1], 16;" :: "r"(dst), "l"(src) : "memory")
#define CP_COMMIT() asm volatile("cp.async.commit_group;" ::: "memory")
#define CP_WAIT(n)  asm volatile("cp.async.wait_group %0;" :: "n"(n) : "memory")

#define LDSM_X4(r0, r1, r2, r3, addr) \
    asm volatile("ldmatrix.sync.aligned.m8n8.x4.shared.b16 {%0,%1,%2,%3}, [%4];" \
                 : "=r"(r0), "=r"(r1), "=r"(r2), "=r"(r3) : "r"(addr))

#define MMA16816(d, a, b) \
    asm volatile("mma.sync.aligned.m16n8k16.row.col.f32.bf16.bf16.f32 " \
                 "{%0,%1,%2,%3}, {%4,%5,%6,%7}, {%8,%9}, {%0,%1,%2,%3};" \
                 : "+f"((d)[0]), "+f"((d)[1]), "+f"((d)[2]), "+f"((d)[3]) \
                 : "r"((a)[0]), "r"((a)[1]), "r"((a)[2]), "r"((a)[3]), \
                   "r"((b)[0]), "r"((b)[1]))

#define CLUSTER_SYNC() do { \
    asm volatile("barrier.cluster.arrive.aligned;" ::: "memory"); \
    asm volatile("barrier.cluster.wait.aligned;" ::: "memory"); \
} while (0)

static __device__ __forceinline__ float dsmem_ld_f32(uint32_t laddr, uint32_t peer) {
    uint32_t raddr;
    asm("mapa.shared::cluster.u32 %0, %1, %2;" : "=r"(raddr) : "r"(laddr), "r"(peer));
    float v;
    asm volatile("ld.shared::cluster.f32 %0, [%1];" : "=f"(v) : "r"(raddr));
    return v;
}

static __device__ __forceinline__ uint32_t pack_bf16x2(float a, float b) {
    __nv_bfloat162 t = __floats2bfloat162_rn(a, b);
    return *reinterpret_cast<uint32_t*>(&t);
}
static __device__ __forceinline__ float bf_lo(uint32_t v) {
    __nv_bfloat162 t = *reinterpret_cast<__nv_bfloat162*>(&v);
    return __bfloat162float(t.x);
}
static __device__ __forceinline__ float bf_hi(uint32_t v) {
    __nv_bfloat162 t = *reinterpret_cast<__nv_bfloat162*>(&v);
    return __bfloat162float(t.y);
}

// ===================== prepass: fp32 -> bf16 for x and W =====================
__global__ void __launch_bounds__(256) cvt_kernel(const float* __restrict__ x,
                                                  const float* __restrict__ W) {
    const size_t XQ = XE / 4;            // float4 count for x
    size_t i = (size_t)blockIdx.x * 256 + threadIdx.x;
    float4 v;
    uint32_t* dst;
    if (i < XQ) {
        v = ((const float4*)x)[i];
        dst = (uint32_t*)&g_xb[i * 4];
    } else {
        size_t j = i - XQ;
        v = ((const float4*)W)[j];
        dst = (uint32_t*)&g_wb[j * 4];
    }
    dst[0] = pack_bf16x2(v.x, v.y);
    dst[1] = pack_bf16x2(v.z, v.w);
}

// ===================== main fused kernel =====================
__global__ void __launch_bounds__(NTHREADS, 1) __cluster_dims__(2, 1, 1)
fwa_kernel(const float* __restrict__ x, const float* __restrict__ bias,
           float* __restrict__ out) {
    extern __shared__ __align__(1024) char smem[];
    const uint32_t sb = smem_u32(smem);
    const int tid  = threadIdx.x;
    const int lane = tid & 31;
    const int wid  = tid >> 5;
    const int wm   = wid & 3;          // warp row block (0..3) * 32 rows
    const int wn   = wid >> 2;         // warp col block (0..3) * 64 cols
    uint32_t rank;
    asm("mov.u32 %0, %%cluster_ctarank;" : "=r"(rank));
    const int    cid      = blockIdx.x >> 1;
    const size_t row_base = (size_t)cid * 128;
    const int    n_base   = (int)rank * 512;

    // bias slice -> smem
    float* sm_bias = (float*)(smem + OFF_BIAS);
    sm_bias[tid] = bias[n_base + tid];

    // ldmatrix per-lane sub-offsets
    const int a_row  = ((lane >> 3) & 1) * 8 + (lane & 7);  // mats: (m0,k0)(m8,k0)(m0,k8)(m8,k8)
    const int a_koff = (lane >> 4) * 8;
    const int b_row  = (lane >> 4) * 8 + (lane & 7);        // mats: (n0,k0)(n0,k8)(n8,k0)(n8,k8)
    const int b_koff = ((lane >> 3) & 1) * 8;

    const char* xb = (const char*)(g_xb + row_base * NDIM);
    __syncthreads();

#pragma unroll 1
    for (int nc = 0; nc < 2; nc++) {
        const char* wb = (const char*)(g_wb + (size_t)(n_base + nc * 256) * NDIM);
        float acc[2][8][4];
#pragma unroll
        for (int mi = 0; mi < 2; mi++)
#pragma unroll
            for (int j = 0; j < 8; j++)
#pragma unroll
                for (int c = 0; c < 4; c++) acc[mi][j][c] = 0.0f;

        // prologue: load kc=0 into stage 0
        {
            const uint32_t da = sb + OFF_A;
            int r = tid >> 2, seg = tid & 3;
            CP_ASYNC16(da + r * 80 + seg * 16, xb + (size_t)r * 2048 + seg * 16);
            const uint32_t db = sb + OFF_B;
#pragma unroll
            for (int ii = 0; ii < 2; ii++) {
                int G = tid + 512 * ii, rb = G >> 2, sg = G & 3;
                CP_ASYNC16(db + rb * 80 + sg * 16, wb + (size_t)rb * 2048 + sg * 16);
            }
            CP_COMMIT();
        }

#pragma unroll 1
        for (int kc = 0; kc < 32; kc++) {
            const int s = kc & 1;
            if (kc < 31) {
                const uint32_t da = sb + OFF_A + (s ^ 1) * A_STG;
                int r = tid >> 2, seg = tid & 3;
                CP_ASYNC16(da + r * 80 + seg * 16,
                           xb + (size_t)r * 2048 + (kc + 1) * 64 + seg * 16);
                const uint32_t db = sb + OFF_B + (s ^ 1) * B_STG;
#pragma unroll
                for (int ii = 0; ii < 2; ii++) {
                    int G = tid + 512 * ii, rb = G >> 2, sg = G & 3;
                    CP_ASYNC16(db + rb * 80 + sg * 16,
                               wb + (size_t)rb * 2048 + (kc + 1) * 64 + sg * 16);
                }
                CP_COMMIT();
                CP_WAIT(1);
            } else {
                CP_WAIT(0);
            }
            __syncthreads();

            const uint32_t baseA = sb + OFF_A + s * A_STG;
            const uint32_t baseB = sb + OFF_B + s * B_STG;
#pragma unroll
            for (int ks = 0; ks < 2; ks++) {
                uint32_t a[2][4];
#pragma unroll
                for (int mi = 0; mi < 2; mi++) {
                    uint32_t addr = baseA + (wm * 32 + mi * 16 + a_row) * 80
                                  + (ks * 16 + a_koff) * 2;
                    LDSM_X4(a[mi][0], a[mi][1], a[mi][2], a[mi][3], addr);
                }
                uint32_t b[8][2];
#pragma unroll
                for (int j2 = 0; j2 < 4; j2++) {
                    uint32_t addr = baseB + (wn * 64 + j2 * 16 + b_row) * 80
                                  + (ks * 16 + b_koff) * 2;
                    uint32_t r0, r1, r2, r3;
                    LDSM_X4(r0, r1, r2, r3, addr);
                    b[j2 * 2][0] = r0;  b[j2 * 2][1] = r1;
                    b[j2 * 2 + 1][0] = r2;  b[j2 * 2 + 1][1] = r3;
                }
#pragma unroll
                for (int mi = 0; mi < 2; mi++)
#pragma unroll
                    for (int j = 0; j < 8; j++)
                        MMA16816(acc[mi][j], a[mi], b[j]);
            }
            __syncthreads();
        }

        // store logits + bias to smem as bf16
#pragma unroll
        for (int mi = 0; mi < 2; mi++) {
            int row = wm * 32 + mi * 16 + (lane >> 2);
#pragma unroll
            for (int j = 0; j < 8; j++) {
                int col = nc * 256 + wn * 64 + j * 8 + (lane & 3) * 2;
                float b0 = sm_bias[col], b1 = sm_bias[col + 1];
                *(uint32_t*)(smem + OFF_L + row * L_STRIDE + col * 2) =
                    pack_bf16x2(acc[mi][j][0] + b0, acc[mi][j][1] + b1);
                *(uint32_t*)(smem + OFF_L + (row + 8) * L_STRIDE + col * 2) =
                    pack_bf16x2(acc[mi][j][2] + b0, acc[mi][j][3] + b1);
            }
        }
        __syncthreads();
    }

    // ---------- softmax pass 1: e = exp(l) (no max-sub: |l| small), partial sums ----------
    {
        int row = tid >> 2, q = tid & 3;
        char* lp = smem + OFF_L + row * L_STRIDE + q * 256;   // 128 cols per thread
        float ssum = 0.0f;
#pragma unroll 8
        for (int i = 0; i < 64; i++) {
            uint32_t v = *(uint32_t*)(lp + i * 4);
            float e0 = __expf(bf_lo(v));
            float e1 = __expf(bf_hi(v));
            ssum += e0 + e1;
            *(uint32_t*)(lp + i * 4) = pack_bf16x2(e0, e1);
        }
        ssum += __shfl_xor_sync(0xFFFFFFFFu, ssum, 1);
        ssum += __shfl_xor_sync(0xFFFFFFFFu, ssum, 2);
        if (q == 0) ((float*)(smem + OFF_S))[row] = ssum;
    }
    __syncthreads();
    CLUSTER_SYNC();   // both CTAs' partial sums visible

    if (tid < 128) {
        float sl = ((float*)(smem + OFF_S))[tid];
        float sr = dsmem_ld_f32(sb + OFF_S + tid * 4, rank ^ 1u);
        ((float*)(smem + OFF_INV))[tid] = 1.0f / (sl + sr);
    }
    __syncthreads();

    // ---------- gating: out = x * (e * invS) + x, coalesced float4 ----------
    {
        const float* xr = x + row_base * 1024 + n_base;
        float*       orow = out + row_base * 1024 + n_base;
        const float* sm_inv = (const float*)(smem + OFF_INV);
#pragma unroll 1
        for (int i = 0; i < 32; i++) {
            int flat4 = tid + 512 * i;          // 0..16383
            int row = flat4 >> 7;               // 128 float4 per row-half
            int c4  = flat4 & 127;
            float inv = sm_inv[row];
            float4 xv = *(const float4*)(xr + (size_t)row * 1024 + c4 * 4);
            uint32_t e01 = *(uint32_t*)(smem + OFF_L + row * L_STRIDE + c4 * 8);
            uint32_t e23 = *(uint32_t*)(smem + OFF_L + row * L_STRIDE + c4 * 8 + 4);
            float4 ov;
            ov.x = fmaf(xv.x, bf_lo(e01) * inv, xv.x);
            ov.y = fmaf(xv.y, bf_hi(e01) * inv, xv.y);
            ov.z = fmaf(xv.z, bf_lo(e23) * inv, xv.z);
            ov.w = fmaf(xv.w, bf_hi(e23) * inv, xv.w);
            *(float4*)(orow + (size_t)row * 1024 + c4 * 4) = ov;
        }
    }
    CLUSTER_SYNC();   // peer may still be DSMEM-reading our sm_s
}

// ===================== host launch =====================
extern "C" void kernel_launch(void* const* d_in, const int* in_sizes, int n_in,
                              void* d_out, int out_size) {
    (void)in_sizes; (void)n_in; (void)out_size;
    const float* x    = (const float*)d_in[0];
    const float* W    = (const float*)d_in[1];
    const float* bias = (const float*)d_in[2];
    float* out = (float*)d_out;

    // prepass: convert x and W to bf16 scratch
    const int cvt_blocks = (XE / 4 + WE / 4) / 256;   // 33792
    cvt_kernel<<<cvt_blocks, 256>>>(x, W);

    // idempotent host-side attribute set (no static guards allowed in this fn)
    cudaFuncSetAttribute(fwa_kernel, cudaFuncAttributeMaxDynamicSharedMemorySize, SMEM_TOTAL);
    fwa_kernel<<<NCTAS, NTHREADS, SMEM_TOTAL>>>(x, bias, out);
}

// round 7
// speedup vs baseline: 1.0782x; 1.0782x over previous
#include <cuda_runtime.h>
#include <cuda_bf16.h>
#include <cstdint>

// ===================== problem constants =====================
#define MROWS 32768
#define NDIM  1024
#define XE    (MROWS * NDIM)       // 33,554,432
#define WE    (NDIM * NDIM)        // 1,048,576
#define NTHREADS 512
#define NCTAS    512               // 256 clusters x 2
#define KITERS   32                // K chunks of 32

// bf16 scratch (static __device__ globals: the sanctioned no-alloc workaround)
__device__ __nv_bfloat16 g_xb[XE];
__device__ __nv_bfloat16 g_wb[WE];

// ===================== smem layout (bytes) =====================
#define OFF_BIAS 0                 // 512 f32
#define OFF_S    2048              // 128 f32 partial expsum
#define OFF_INV  2560              // 128 f32 1/S
#define OFF_A    4096              // 3 stages x 10240 (128 rows x 80B padded)
#define A_STG    10240
#define OFF_B    34816             // 3 stages x 20480 (256 rows x 80B padded)
#define B_STG    20480
#define OFF_L    96256             // 128 x 1040B logits (520 bf16/row, padded)
#define L_STRIDE 1040
#define SMEM_TOTAL 229376          // <= 232448 cap

// ===================== helpers =====================
static __device__ __forceinline__ uint32_t smem_u32(const void* p) {
    uint32_t a;
    asm("{ .reg .u64 t; cvta.to.shared.u64 t, %1; cvt.u32.u64 %0, t; }" : "=r"(a) : "l"(p));
    return a;
}

#define CP_ASYNC16(dst, src) \
    asm volatile("cp.async.cg.shared.global [%0], [%1], 16;" :: "r"(dst), "l"(src) : "memory")
#define CP_COMMIT() asm volatile("cp.async.commit_group;" ::: "memory")
#define CP_WAIT(n)  asm volatile("cp.async.wait_group %0;" :: "n"(n) : "memory")

#define LDSM_X4(r0, r1, r2, r3, addr) \
    asm volatile("ldmatrix.sync.aligned.m8n8.x4.shared.b16 {%0,%1,%2,%3}, [%4];" \
                 : "=r"(r0), "=r"(r1), "=r"(r2), "=r"(r3) : "r"(addr))

#define MMA16816(d, a, b) \
    asm volatile("mma.sync.aligned.m16n8k16.row.col.f32.bf16.bf16.f32 " \
                 "{%0,%1,%2,%3}, {%4,%5,%6,%7}, {%8,%9}, {%0,%1,%2,%3};" \
                 : "+f"((d)[0]), "+f"((d)[1]), "+f"((d)[2]), "+f"((d)[3]) \
                 : "r"((a)[0]), "r"((a)[1]), "r"((a)[2]), "r"((a)[3]), \
                   "r"((b)[0]), "r"((b)[1]))

#define CLUSTER_SYNC() do { \
    asm volatile("barrier.cluster.arrive.aligned;" ::: "memory"); \
    asm volatile("barrier.cluster.wait.aligned;" ::: "memory"); \
} while (0)

static __device__ __forceinline__ float dsmem_ld_f32(uint32_t laddr, uint32_t peer) {
    uint32_t raddr;
    asm("mapa.shared::cluster.u32 %0, %1, %2;" : "=r"(raddr) : "r"(laddr), "r"(peer));
    float v;
    asm volatile("ld.shared::cluster.f32 %0, [%1];" : "=f"(v) : "r"(raddr));
    return v;
}

static __device__ __forceinline__ uint32_t pack_bf16x2(float a, float b) {
    __nv_bfloat162 t = __floats2bfloat162_rn(a, b);
    return *reinterpret_cast<uint32_t*>(&t);
}
static __device__ __forceinline__ float bf_lo(uint32_t v) {
    __nv_bfloat162 t = *reinterpret_cast<__nv_bfloat162*>(&v);
    return __bfloat162float(t.x);
}
static __device__ __forceinline__ float bf_hi(uint32_t v) {
    __nv_bfloat162 t = *reinterpret_cast<__nv_bfloat162*>(&v);
    return __bfloat162float(t.y);
}

// ===================== prepass: fp32 -> bf16 for x and W =====================
__global__ void __launch_bounds__(256) cvt_kernel(const float* __restrict__ x,
                                                  const float* __restrict__ W) {
    const size_t XQ = XE / 4;            // float4 count for x
    size_t i = (size_t)blockIdx.x * 256 + threadIdx.x;
    float4 v;
    uint32_t* dst;
    if (i < XQ) {
        v = ((const float4*)x)[i];
        dst = (uint32_t*)&g_xb[i * 4];
    } else {
        size_t j = i - XQ;
        v = ((const float4*)W)[j];
        dst = (uint32_t*)&g_wb[j * 4];
    }
    dst[0] = pack_bf16x2(v.x, v.y);
    dst[1] = pack_bf16x2(v.z, v.w);
}

// load one K-chunk (32 cols) of A(128 rows) + B(256 rows) into a stage
static __device__ __forceinline__ void load_chunk(uint32_t sb, int stage, int kc,
                                                  const char* xb, const char* wb, int tid) {
    const uint32_t da = sb + OFF_A + stage * A_STG;
    int r = tid >> 2, seg = tid & 3;
    CP_ASYNC16(da + r * 80 + seg * 16, xb + (size_t)r * 2048 + (size_t)kc * 64 + seg * 16);
    const uint32_t db = sb + OFF_B + stage * B_STG;
#pragma unroll
    for (int ii = 0; ii < 2; ii++) {
        int G = tid + 512 * ii, rb = G >> 2, sg = G & 3;
        CP_ASYNC16(db + rb * 80 + sg * 16, wb + (size_t)rb * 2048 + (size_t)kc * 64 + sg * 16);
    }
}

// ===================== main fused kernel =====================
__global__ void __launch_bounds__(NTHREADS, 1) __cluster_dims__(2, 1, 1)
fwa_kernel(const float* __restrict__ x, const float* __restrict__ bias,
           float* __restrict__ out) {
    extern __shared__ __align__(1024) char smem[];
    const uint32_t sb = smem_u32(smem);
    const int tid  = threadIdx.x;
    const int lane = tid & 31;
    const int wid  = tid >> 5;
    const int wm   = wid & 3;          // warp row block (0..3) * 32 rows
    const int wn   = wid >> 2;         // warp col block (0..3) * 64 cols
    uint32_t rank;
    asm("mov.u32 %0, %%cluster_ctarank;" : "=r"(rank));
    const int    cid      = blockIdx.x >> 1;
    const size_t row_base = (size_t)cid * 128;
    const int    n_base   = (int)rank * 512;

    // bias slice -> smem
    float* sm_bias = (float*)(smem + OFF_BIAS);
    sm_bias[tid] = bias[n_base + tid];

    // ldmatrix per-lane sub-offsets
    const int a_row  = ((lane >> 3) & 1) * 8 + (lane & 7);  // mats: (m0,k0)(m8,k0)(m0,k8)(m8,k8)
    const int a_koff = (lane >> 4) * 8;
    const int b_row  = (lane >> 4) * 8 + (lane & 7);        // mats: (n0,k0)(n0,k8)(n8,k0)(n8,k8)
    const int b_koff = ((lane >> 3) & 1) * 8;

    const char* xb = (const char*)(g_xb + row_base * NDIM);
    __syncthreads();

#pragma unroll 1
    for (int nc = 0; nc < 2; nc++) {
        const char* wb = (const char*)(g_wb + (size_t)(n_base + nc * 256) * NDIM);
        float acc[2][8][4];
#pragma unroll
        for (int mi = 0; mi < 2; mi++)
#pragma unroll
            for (int j = 0; j < 8; j++)
#pragma unroll
                for (int c = 0; c < 4; c++) acc[mi][j][c] = 0.0f;

        // prologue: chunks 0,1 into stages 0,1 (separate commit groups)
        load_chunk(sb, 0, 0, xb, wb, tid);
        CP_COMMIT();
        load_chunk(sb, 1, 1, xb, wb, tid);
        CP_COMMIT();

#pragma unroll 1
        for (int kc = 0; kc < KITERS; kc++) {
            // wait for chunk kc's data; once no more issues remain, drain fully
            if (kc + 2 < KITERS) { CP_WAIT(1); } else { CP_WAIT(0); }
            __syncthreads();   // also orders: everyone finished reading stage (kc+2)%3 last iter

            // refill the freed stage with chunk kc+2
            if (kc + 2 < KITERS) {
                load_chunk(sb, (kc + 2) % 3, kc + 2, xb, wb, tid);
                CP_COMMIT();
            }

            const int s = kc % 3;
            const uint32_t baseA = sb + OFF_A + s * A_STG;
            const uint32_t baseB = sb + OFF_B + s * B_STG;
#pragma unroll
            for (int ks = 0; ks < 2; ks++) {
                uint32_t a[2][4];
#pragma unroll
                for (int mi = 0; mi < 2; mi++) {
                    uint32_t addr = baseA + (wm * 32 + mi * 16 + a_row) * 80
                                  + (ks * 16 + a_koff) * 2;
                    LDSM_X4(a[mi][0], a[mi][1], a[mi][2], a[mi][3], addr);
                }
                uint32_t b[8][2];
#pragma unroll
                for (int j2 = 0; j2 < 4; j2++) {
                    uint32_t addr = baseB + (wn * 64 + j2 * 16 + b_row) * 80
                                  + (ks * 16 + b_koff) * 2;
                    uint32_t r0, r1, r2, r3;
                    LDSM_X4(r0, r1, r2, r3, addr);
                    b[j2 * 2][0] = r0;  b[j2 * 2][1] = r1;
                    b[j2 * 2 + 1][0] = r2;  b[j2 * 2 + 1][1] = r3;
                }
#pragma unroll
                for (int mi = 0; mi < 2; mi++)
#pragma unroll
                    for (int j = 0; j < 8; j++)
                        MMA16816(acc[mi][j], a[mi], b[j]);
            }
        }
        __syncthreads();   // all warps done with final stages before logit store / next nc

        // store logits + bias to smem as bf16
#pragma unroll
        for (int mi = 0; mi < 2; mi++) {
            int row = wm * 32 + mi * 16 + (lane >> 2);
#pragma unroll
            for (int j = 0; j < 8; j++) {
                int col = nc * 256 + wn * 64 + j * 8 + (lane & 3) * 2;
                float b0 = sm_bias[col], b1 = sm_bias[col + 1];
                *(uint32_t*)(smem + OFF_L + row * L_STRIDE + col * 2) =
                    pack_bf16x2(acc[mi][j][0] + b0, acc[mi][j][1] + b1);
                *(uint32_t*)(smem + OFF_L + (row + 8) * L_STRIDE + col * 2) =
                    pack_bf16x2(acc[mi][j][2] + b0, acc[mi][j][3] + b1);
            }
        }
        __syncthreads();
    }

    // ---------- softmax pass 1: e = exp(l) (no max-sub: |l| small), partial sums ----------
    {
        int row = tid >> 2, q = tid & 3;
        char* lp = smem + OFF_L + row * L_STRIDE + q * 256;   // 128 cols per thread
        float ssum = 0.0f;
#pragma unroll 8
        for (int i = 0; i < 64; i++) {
            uint32_t v = *(uint32_t*)(lp + i * 4);
            float e0 = __expf(bf_lo(v));
            float e1 = __expf(bf_hi(v));
            ssum += e0 + e1;
            *(uint32_t*)(lp + i * 4) = pack_bf16x2(e0, e1);
        }
        ssum += __shfl_xor_sync(0xFFFFFFFFu, ssum, 1);
        ssum += __shfl_xor_sync(0xFFFFFFFFu, ssum, 2);
        if (q == 0) ((float*)(smem + OFF_S))[row] = ssum;
    }
    __syncthreads();
    CLUSTER_SYNC();   // both CTAs' partial sums visible

    if (tid < 128) {
        float sl = ((float*)(smem + OFF_S))[tid];
        float sr = dsmem_ld_f32(sb + OFF_S + tid * 4, rank ^ 1u);
        ((float*)(smem + OFF_INV))[tid] = 1.0f / (sl + sr);
    }
    __syncthreads();

    // ---------- gating: out = x * (e * invS) + x, coalesced float4 ----------
    {
        const float* xr = x + row_base * 1024 + n_base;
        float*       orow = out + row_base * 1024 + n_base;
        const float* sm_inv = (const float*)(smem + OFF_INV);
#pragma unroll 1
        for (int i = 0; i < 32; i++) {
            int flat4 = tid + 512 * i;          // 0..16383
            int row = flat4 >> 7;               // 128 float4 per row-half
            int c4  = flat4 & 127;
            float inv = sm_inv[row];
            float4 xv = *(const float4*)(xr + (size_t)row * 1024 + c4 * 4);
            uint32_t e01 = *(uint32_t*)(smem + OFF_L + row * L_STRIDE + c4 * 8);
            uint32_t e23 = *(uint32_t*)(smem + OFF_L + row * L_STRIDE + c4 * 8 + 4);
            float4 ov;
            ov.x = fmaf(xv.x, bf_lo(e01) * inv, xv.x);
            ov.y = fmaf(xv.y, bf_hi(e01) * inv, xv.y);
            ov.z = fmaf(xv.z, bf_lo(e23) * inv, xv.z);
            ov.w = fmaf(xv.w, bf_hi(e23) * inv, xv.w);
            *(float4*)(orow + (size_t)row * 1024 + c4 * 4) = ov;
        }
    }
    CLUSTER_SYNC();   // peer may still be DSMEM-reading our sm_s
}

// ===================== host launch =====================
extern "C" void kernel_launch(void* const* d_in, const int* in_sizes, int n_in,
                              void* d_out, int out_size) {
    (void)in_sizes; (void)n_in; (void)out_size;
    const float* x    = (const float*)d_in[0];
    const float* W    = (const float*)d_in[1];
    const float* bias = (const float*)d_in[2];
    float* out = (float*)d_out;

    // prepass: convert x and W to bf16 scratch
    const int cvt_blocks = (XE / 4 + WE / 4) / 256;   // 33792
    cvt_kernel<<<cvt_blocks, 256>>>(x, W);

    // idempotent host-side attribute set (no static guards allowed in this fn)
    cudaFuncSetAttribute(fwa_kernel, cudaFuncAttributeMaxDynamicSharedMemorySize, SMEM_TOTAL);
    fwa_kernel<<<NCTAS, NTHREADS, SMEM_TOTAL>>>(x, bias, out);
}

// round 8
// speedup vs baseline: 1.1969x; 1.1101x over previous
#include <cuda_runtime.h>
#include <cuda_bf16.h>
#include <cstdint>

// ===================== problem constants =====================
#define MROWS 32768
#define NDIM  1024
#define XE    (MROWS * NDIM)
#define WE    (NDIM * NDIM)
#define NTHREADS 512
#define NCTAS    512               // 256 clusters x 2
#define KITERS   16                // K chunks of 64
#define NSTAGES  3

// global scratch (static __device__: the sanctioned no-alloc workaround)
__device__ __nv_bfloat16 g_xb[XE];
__device__ __nv_bfloat16 g_wb[WE];
__device__ __nv_bfloat16 g_e[XE];      // exp(logit) values

// ===================== smem layout (bytes) =====================
#define OFF_S    0                 // 128 f32 row expsum (atomicAdd target)
#define OFF_INV  512               // 128 f32 1/S
#define OFF_A    1024              // 3 stages x 16384 (128 rows x 128B, swizzled)
#define A_STG    16384
#define OFF_B    50176             // 3 stages x 32768 (256 rows x 128B, swizzled)
#define B_STG    32768
#define SMEM_TOTAL 148480

// ===================== helpers =====================
static __device__ __forceinline__ uint32_t smem_u32(const void* p) {
    uint32_t a;
    asm("{ .reg .u64 t; cvta.to.shared.u64 t, %1; cvt.u32.u64 %0, t; }" : "=r"(a) : "l"(p));
    return a;
}

#define CP_ASYNC16(dst, src) \
    asm volatile("cp.async.cg.shared.global [%0], [%1], 16;" :: "r"(dst), "l"(src) : "memory")
#define CP_COMMIT() asm volatile("cp.async.commit_group;" ::: "memory")
#define CP_WAIT(n)  asm volatile("cp.async.wait_group %0;" :: "n"(n) : "memory")

#define LDSM_X4(r0, r1, r2, r3, addr) \
    asm volatile("ldmatrix.sync.aligned.m8n8.x4.shared.b16 {%0,%1,%2,%3}, [%4];" \
                 : "=r"(r0), "=r"(r1), "=r"(r2), "=r"(r3) : "r"(addr))

#define MMA16816(d, a, b) \
    asm volatile("mma.sync.aligned.m16n8k16.row.col.f32.bf16.bf16.f32 " \
                 "{%0,%1,%2,%3}, {%4,%5,%6,%7}, {%8,%9}, {%0,%1,%2,%3};" \
                 : "+f"((d)[0]), "+f"((d)[1]), "+f"((d)[2]), "+f"((d)[3]) \
                 : "r"((a)[0]), "r"((a)[1]), "r"((a)[2]), "r"((a)[3]), \
                   "r"((b)[0]), "r"((b)[1]))

#define CLUSTER_SYNC() do { \
    asm volatile("barrier.cluster.arrive.aligned;" ::: "memory"); \
    asm volatile("barrier.cluster.wait.aligned;" ::: "memory"); \
} while (0)

static __device__ __forceinline__ float dsmem_ld_f32(uint32_t laddr, uint32_t peer) {
    uint32_t raddr;
    asm("mapa.shared::cluster.u32 %0, %1, %2;" : "=r"(raddr) : "r"(laddr), "r"(peer));
    float v;
    asm volatile("ld.shared::cluster.f32 %0, [%1];" : "=f"(v) : "r"(raddr));
    return v;
}

static __device__ __forceinline__ uint32_t pack_bf16x2(float a, float b) {
    __nv_bfloat162 t = __floats2bfloat162_rn(a, b);
    return *reinterpret_cast<uint32_t*>(&t);
}
static __device__ __forceinline__ float bf_lo(uint32_t v) {
    __nv_bfloat162 t = *reinterpret_cast<__nv_bfloat162*>(&v);
    return __bfloat162float(t.x);
}
static __device__ __forceinline__ float bf_hi(uint32_t v) {
    __nv_bfloat162 t = *reinterpret_cast<__nv_bfloat162*>(&v);
    return __bfloat162float(t.y);
}

// ===================== prepass: fp32 -> bf16 for x and W =====================
__global__ void __launch_bounds__(256) cvt_kernel(const float* __restrict__ x,
                                                  const float* __restrict__ W) {
    const size_t XQ = XE / 4;
    size_t i = (size_t)blockIdx.x * 256 + threadIdx.x;
    float4 v;
    uint32_t* dst;
    if (i < XQ) {
        v = ((const float4*)x)[i];
        dst = (uint32_t*)&g_xb[i * 4];
    } else {
        size_t j = i - XQ;
        v = ((const float4*)W)[j];
        dst = (uint32_t*)&g_wb[j * 4];
    }
    dst[0] = pack_bf16x2(v.x, v.y);
    dst[1] = pack_bf16x2(v.z, v.w);
}

// load one K64 chunk: A 128 rows x 128B, B 256 rows x 128B, XOR-swizzled
static __device__ __forceinline__ void load_chunk(uint32_t sb, int stage, int kc,
                                                  const char* xb, const char* wb, int tid) {
    const uint32_t abase = sb + OFF_A + stage * A_STG;
#pragma unroll
    for (int ii = 0; ii < 2; ii++) {
        int G = tid + 512 * ii;
        int r = G >> 3, s = G & 7;
        CP_ASYNC16(abase + r * 128 + ((s ^ (r & 7)) << 4),
                   xb + (size_t)r * 2048 + (size_t)kc * 128 + s * 16);
    }
    const uint32_t bbase = sb + OFF_B + stage * B_STG;
#pragma unroll
    for (int ii = 0; ii < 4; ii++) {
        int G = tid + 512 * ii;
        int r = G >> 3, s = G & 7;
        CP_ASYNC16(bbase + r * 128 + ((s ^ (r & 7)) << 4),
                   wb + (size_t)r * 2048 + (size_t)kc * 128 + s * 16);
    }
}

// ===================== main fused kernel =====================
__global__ void __launch_bounds__(NTHREADS, 1) __cluster_dims__(2, 1, 1)
fwa_kernel(const float* __restrict__ x, const float* __restrict__ bias,
           float* __restrict__ out) {
    extern __shared__ __align__(1024) char smem[];
    const uint32_t sb = smem_u32(smem);
    const int tid  = threadIdx.x;
    const int lane = tid & 31;
    const int wid  = tid >> 5;
    const int wm   = wid & 3;          // warp row block * 32
    const int wn   = wid >> 2;         // warp col block * 64
    uint32_t rank;
    asm("mov.u32 %0, %%cluster_ctarank;" : "=r"(rank));
    const int    cid      = blockIdx.x >> 1;
    const size_t row_base = (size_t)cid * 128;
    const int    n_base   = (int)rank * 512;

    float* sm_s   = (float*)(smem + OFF_S);
    float* sm_inv = (float*)(smem + OFF_INV);
    if (tid < 128) sm_s[tid] = 0.0f;

    // ldmatrix per-lane sub-offsets
    const int a_row  = ((lane >> 3) & 1) * 8 + (lane & 7);
    const int a_cb   = (lane >> 4);          // 0/1 : 16B block within 32B ks step
    const int b_row  = (lane >> 4) * 8 + (lane & 7);
    const int b_cb   = ((lane >> 3) & 1);

    const char* xb = (const char*)(g_xb + row_base * NDIM);
    __syncthreads();

#pragma unroll 1
    for (int nc = 0; nc < 2; nc++) {
        const char* wb = (const char*)(g_wb + (size_t)(n_base + nc * 256) * NDIM);
        float acc[2][8][4];
#pragma unroll
        for (int mi = 0; mi < 2; mi++)
#pragma unroll
            for (int j = 0; j < 8; j++)
#pragma unroll
                for (int c = 0; c < 4; c++) acc[mi][j][c] = 0.0f;

        load_chunk(sb, 0, 0, xb, wb, tid);
        CP_COMMIT();
        load_chunk(sb, 1, 1, xb, wb, tid);
        CP_COMMIT();

#pragma unroll 1
        for (int kc = 0; kc < KITERS; kc++) {
            if (kc + 2 < KITERS) { CP_WAIT(1); } else { CP_WAIT(0); }
            __syncthreads();   // orders prior reads of the stage being refilled

            if (kc + 2 < KITERS) {
                load_chunk(sb, (kc + 2) % NSTAGES, kc + 2, xb, wb, tid);
                CP_COMMIT();
            }

            const int s = kc % NSTAGES;
            const uint32_t baseA = sb + OFF_A + s * A_STG;
            const uint32_t baseB = sb + OFF_B + s * B_STG;
#pragma unroll
            for (int ks = 0; ks < 4; ks++) {
                uint32_t a[2][4];
#pragma unroll
                for (int mi = 0; mi < 2; mi++) {
                    int rT = wm * 32 + mi * 16 + a_row;
                    int cb = ks * 2 + a_cb;
                    uint32_t addr = baseA + rT * 128 + ((cb ^ (rT & 7)) << 4);
                    LDSM_X4(a[mi][0], a[mi][1], a[mi][2], a[mi][3], addr);
                }
                uint32_t b[8][2];
#pragma unroll
                for (int j2 = 0; j2 < 4; j2++) {
                    int rT = wn * 64 + j2 * 16 + b_row;
                    int cb = ks * 2 + b_cb;
                    uint32_t addr = baseB + rT * 128 + ((cb ^ (rT & 7)) << 4);
                    uint32_t r0, r1, r2, r3;
                    LDSM_X4(r0, r1, r2, r3, addr);
                    b[j2 * 2][0] = r0;      b[j2 * 2][1] = r1;
                    b[j2 * 2 + 1][0] = r2;  b[j2 * 2 + 1][1] = r3;
                }
#pragma unroll
                for (int mi = 0; mi < 2; mi++)
#pragma unroll
                    for (int j = 0; j < 8; j++)
                        MMA16816(acc[mi][j], a[mi], b[j]);
            }
        }
        __syncthreads();   // all reads of final stages done before next nc refill

        // ---- fused epilogue: exp(acc+bias), row sums, e -> global bf16 ----
#pragma unroll
        for (int mi = 0; mi < 2; mi++) {
            int r0 = wm * 32 + mi * 16 + (lane >> 2);
            int r1 = r0 + 8;
            float s0 = 0.0f, s1 = 0.0f;
#pragma unroll
            for (int j = 0; j < 8; j++) {
                int gcol = n_base + nc * 256 + wn * 64 + j * 8 + (lane & 3) * 2;
                float2 bv = __ldg((const float2*)(bias + gcol));
                float e0 = __expf(acc[mi][j][0] + bv.x);
                float e1 = __expf(acc[mi][j][1] + bv.y);
                float e2 = __expf(acc[mi][j][2] + bv.x);
                float e3 = __expf(acc[mi][j][3] + bv.y);
                s0 += e0 + e1;
                s1 += e2 + e3;
                *(uint32_t*)(g_e + (row_base + r0) * 1024 + gcol) = pack_bf16x2(e0, e1);
                *(uint32_t*)(g_e + (row_base + r1) * 1024 + gcol) = pack_bf16x2(e2, e3);
            }
            s0 += __shfl_xor_sync(0xFFFFFFFFu, s0, 1);
            s0 += __shfl_xor_sync(0xFFFFFFFFu, s0, 2);
            s1 += __shfl_xor_sync(0xFFFFFFFFu, s1, 1);
            s1 += __shfl_xor_sync(0xFFFFFFFFu, s1, 2);
            if ((lane & 3) == 0) {
                atomicAdd(&sm_s[r0], s0);
                atomicAdd(&sm_s[r1], s1);
            }
        }
    }

    __syncthreads();
    CLUSTER_SYNC();   // both CTAs' partial sums finalized

    if (tid < 128) {
        float sl = sm_s[tid];
        float sr = dsmem_ld_f32(sb + OFF_S + tid * 4, rank ^ 1u);
        sm_inv[tid] = 1.0f / (sl + sr);
    }
    __syncthreads();

    // ---------- gating: out = x * (e * invS) + x, coalesced float4 ----------
    {
        const float* xr   = x   + row_base * 1024 + n_base;
        float*       orow = out + row_base * 1024 + n_base;
        const __nv_bfloat16* er = g_e + row_base * 1024 + n_base;
#pragma unroll 1
        for (int i = 0; i < 32; i++) {
            int flat4 = tid + 512 * i;          // 0..16383
            int row = flat4 >> 7;
            int c4  = flat4 & 127;
            float inv = sm_inv[row];
            float4 xv = *(const float4*)(xr + (size_t)row * 1024 + c4 * 4);
            uint2  ev = *(const uint2*)(er + (size_t)row * 1024 + c4 * 4);
            float4 ov;
            ov.x = fmaf(xv.x, bf_lo(ev.x) * inv, xv.x);
            ov.y = fmaf(xv.y, bf_hi(ev.x) * inv, xv.y);
            ov.z = fmaf(xv.z, bf_lo(ev.y) * inv, xv.z);
            ov.w = fmaf(xv.w, bf_hi(ev.y) * inv, xv.w);
            *(float4*)(orow + (size_t)row * 1024 + c4 * 4) = ov;
        }
    }
    CLUSTER_SYNC();   // peer may still be DSMEM-reading our sm_s
}

// ===================== host launch =====================
extern "C" void kernel_launch(void* const* d_in, const int* in_sizes, int n_in,
                              void* d_out, int out_size) {
    (void)in_sizes; (void)n_in; (void)out_size;
    const float* x    = (const float*)d_in[0];
    const float* W    = (const float*)d_in[1];
    const float* bias = (const float*)d_in[2];
    float* out = (float*)d_out;

    const int cvt_blocks = (XE / 4 + WE / 4) / 256;
    cvt_kernel<<<cvt_blocks, 256>>>(x, W);

    cudaFuncSetAttribute(fwa_kernel, cudaFuncAttributeMaxDynamicSharedMemorySize, SMEM_TOTAL);
    fwa_kernel<<<NCTAS, NTHREADS, SMEM_TOTAL>>>(x, bias, out);
}